// round 1
// baseline (speedup 1.0000x reference)
#include <cuda_runtime.h>
#include <math.h>

#define TTOK 2048
#define DMOD 1024
#define FDIM 4096
#define SEQ  1024
#define NBAT 2
#define NH   16
#define HDM  64
#define NE   8
#define VOC  32000
#define NL   3

// ---------------- scratch (static device globals; no allocation) ----------------
__device__ float g_x   [TTOK*DMOD];
__device__ float g_q   [TTOK*DMOD];
__device__ float g_k   [TTOK*DMOD];
__device__ float g_v   [TTOK*DMOD];
__device__ float g_t1  [TTOK*DMOD];
__device__ float g_sc  [NBAT*NH*SEQ*SEQ];      // 128 MB attention scores
__device__ float g_ffh [TTOK*FDIM];
__device__ float g_moeh[NE*TTOK*FDIM];         // 256 MB expert hidden (padded per-expert)
__device__ float g_moe [TTOK*DMOD];
__device__ float g_xn  [TTOK*DMOD];
__device__ int   g_cnt [NE];
__device__ int   g_perm[NE*TTOK];
__device__ float g_pw  [NE*TTOK];

// ---------------- generic tiled GEMM ----------------
struct GP {
    const float* A; const float* B; float* C;
    const float* bias;
    int M, N, K;
    int lda, ldb, ldc;
    int bh;                        // z -> (b2 = z/bh, b1 = z%bh)
    long long sA1, sA2, sB1, sB2, sC1, sC2, sBias1;
    const int*   counts;           // per-z M override (or null)
    const int*   rowmap;           // gather map for A rows / scatter map for output rows
    int          mapStride;
    const float* rowsc;            // per-row scale for scatter
    float*       scat; int scat_ld;
};

enum { EP_STORE = 0, EP_RELU = 1, EP_SCATTER = 2 };

template<int BM, int BN, int BK, int TM, int TN, bool TB, bool GATHER, int MODE>
__global__ __launch_bounds__(256) void gemm_k(GP p) {
    const int z  = blockIdx.z;
    const int b2 = z / p.bh, b1 = z % p.bh;
    const float* A = p.A + b2 * p.sA2 + b1 * p.sA1;
    const float* B = p.B + b2 * p.sB2 + b1 * p.sB1;
    const int M = p.counts ? p.counts[z] : p.M;
    const int row0 = blockIdx.y * BM;
    if (row0 >= M) return;
    const int col0 = blockIdx.x * BN;

    __shared__ float As[BK][BM];
    __shared__ float Bs[BK][BN];

    const int tid = threadIdx.x;           // 256 threads
    const int tr  = tid / (BN / TN);
    const int tc  = tid % (BN / TN);

    float acc[TM][TN];
#pragma unroll
    for (int i = 0; i < TM; i++)
#pragma unroll
        for (int j = 0; j < TN; j++) acc[i][j] = 0.f;

    // A loader: BM*BK == 256*4 floats -> one float4 per thread
    const int aRow = tid / (BK / 4);
    const int aK   = (tid % (BK / 4)) * 4;
    const int aGRow = row0 + aRow;
    const bool aValid = aGRow < M;
    const int* rmap = (GATHER || MODE == EP_SCATTER)
                      ? p.rowmap + (long long)z * p.mapStride : nullptr;
    long long aBase;
    if (GATHER) {
        int tok = aValid ? rmap[aGRow] : 0;
        aBase = (long long)tok * p.lda;
    } else {
        aBase = (long long)aGRow * p.lda;
    }

    const int nK = p.K / BK;
    for (int kt = 0; kt < nK; kt++) {
        const int k0 = kt * BK;
        // ---- load A tile (transposed into shared) ----
        float4 av = make_float4(0.f, 0.f, 0.f, 0.f);
        if (aValid) av = *reinterpret_cast<const float4*>(A + aBase + k0 + aK);
        As[aK + 0][aRow] = av.x; As[aK + 1][aRow] = av.y;
        As[aK + 2][aRow] = av.z; As[aK + 3][aRow] = av.w;
        // ---- load B tile ----
        if (!TB) {
            if (BN == 128) {
                const int bRow = tid / 32;
                const int bCol = (tid % 32) * 4;
                float4 bv = make_float4(0.f, 0.f, 0.f, 0.f);
                if (col0 + bCol < p.N)
                    bv = *reinterpret_cast<const float4*>(B + (long long)(k0 + bRow) * p.ldb + col0 + bCol);
                *reinterpret_cast<float4*>(&Bs[bRow][bCol]) = bv;
            } else {  // BN == 64
                const int bRow = tid / 32;
                const int bCol = (tid % 32) * 2;
                float2 bv = make_float2(0.f, 0.f);
                if (col0 + bCol < p.N)
                    bv = *reinterpret_cast<const float2*>(B + (long long)(k0 + bRow) * p.ldb + col0 + bCol);
                Bs[bRow][bCol] = bv.x; Bs[bRow][bCol + 1] = bv.y;
            }
        } else {
            // B stored [N, K] row-major; Bs[k][n] = B[n*ldb + k]
            const int bN = tid / (BK / 4);
            const int bK = (tid % (BK / 4)) * 4;
            float4 bv = make_float4(0.f, 0.f, 0.f, 0.f);
            if (col0 + bN < p.N)
                bv = *reinterpret_cast<const float4*>(B + (long long)(col0 + bN) * p.ldb + k0 + bK);
            Bs[bK + 0][bN] = bv.x; Bs[bK + 1][bN] = bv.y;
            Bs[bK + 2][bN] = bv.z; Bs[bK + 3][bN] = bv.w;
        }
        __syncthreads();
        // ---- compute ----
#pragma unroll
        for (int k = 0; k < BK; k++) {
            float af[TM], bf[TN];
#pragma unroll
            for (int i = 0; i < TM; i++) af[i] = As[k][tr * TM + i];
#pragma unroll
            for (int j = 0; j < TN; j++) bf[j] = Bs[k][tc * TN + j];
#pragma unroll
            for (int i = 0; i < TM; i++)
#pragma unroll
                for (int j = 0; j < TN; j++) acc[i][j] += af[i] * bf[j];
        }
        __syncthreads();
    }

    // ---- epilogue ----
    const float* bias = p.bias ? p.bias + b1 * p.sBias1 : nullptr;
    float* Cp = nullptr;
    if (MODE != EP_SCATTER) Cp = p.C + b2 * p.sC2 + b1 * p.sC1;
#pragma unroll
    for (int i = 0; i < TM; i++) {
        const int r = row0 + tr * TM + i;
        if (r >= M) continue;
#pragma unroll
        for (int j = 0; j < TN; j++) {
            const int c = col0 + tc * TN + j;
            if (c >= p.N) continue;
            float vv = acc[i][j];
            if (bias) vv += bias[c];
            if (MODE == EP_RELU) vv = fmaxf(vv, 0.f);
            if (MODE == EP_SCATTER) {
                const int tok = rmap[r];
                const float w = p.rowsc[(long long)z * p.mapStride + r];
                atomicAdd(p.scat + (long long)tok * p.scat_ld + c, w * vv);
            } else {
                Cp[(long long)r * p.ldc + c] = vv;
            }
        }
    }
}

// ---------------- embedding + positional encoding ----------------
__global__ void embed_k(const int* __restrict__ src, const float* __restrict__ emb,
                        float* __restrict__ x) {
    const int t = blockIdx.x;
    const int s = t % SEQ;
    const int tok = src[t];
    const float c = -logf(10000.0f) / (float)DMOD;
    for (int d = threadIdx.x; d < DMOD; d += blockDim.x) {
        const int i = d >> 1;
        const float div = expf((float)(2 * i) * c);
        const float ang = (float)s * div;
        const float pe = (d & 1) ? cosf(ang) : sinf(ang);
        x[(long long)t * DMOD + d] = emb[(long long)tok * DMOD + d] * 32.0f + pe;
    }
}

// ---------------- layernorm (optionally residual: out = LN(a + res)) ----------------
__global__ void ln_k(const float* __restrict__ a, const float* __restrict__ res,
                     const float* __restrict__ g, const float* __restrict__ be,
                     float* __restrict__ out) {
    const int row = blockIdx.x;
    const int tid = threadIdx.x;  // 256, 4 floats each
    float4 v = reinterpret_cast<const float4*>(a + (long long)row * DMOD)[tid];
    if (res) {
        float4 r = reinterpret_cast<const float4*>(res + (long long)row * DMOD)[tid];
        v.x += r.x; v.y += r.y; v.z += r.z; v.w += r.w;
    }
    float s  = v.x + v.y + v.z + v.w;
    float sq = v.x * v.x + v.y * v.y + v.z * v.z + v.w * v.w;
    __shared__ float rs[8], rq[8];
    for (int o = 16; o > 0; o >>= 1) {
        s  += __shfl_xor_sync(0xffffffffu, s,  o);
        sq += __shfl_xor_sync(0xffffffffu, sq, o);
    }
    if ((tid & 31) == 0) { rs[tid >> 5] = s; rq[tid >> 5] = sq; }
    __syncthreads();
    __shared__ float s_mu, s_inv;
    if (tid == 0) {
        float S = 0.f, Q = 0.f;
        for (int i = 0; i < 8; i++) { S += rs[i]; Q += rq[i]; }
        const float mu  = S / (float)DMOD;
        const float var = Q / (float)DMOD - mu * mu;
        s_mu = mu; s_inv = rsqrtf(var + 1e-5f);
    }
    __syncthreads();
    const float mu = s_mu, inv = s_inv;
    const float4 gv = reinterpret_cast<const float4*>(g)[tid];
    const float4 bv = reinterpret_cast<const float4*>(be)[tid];
    float4 o;
    o.x = (v.x - mu) * inv * gv.x + bv.x;
    o.y = (v.y - mu) * inv * gv.y + bv.y;
    o.z = (v.z - mu) * inv * gv.z + bv.z;
    o.w = (v.w - mu) * inv * gv.w + bv.w;
    reinterpret_cast<float4*>(out + (long long)row * DMOD)[tid] = o;
}

// ---------------- row softmax over scores (with 1/sqrt(hd) scale) ----------------
__global__ void softmax_k(float* __restrict__ sc) {
    const float scale = 0.125f;
    float* p = sc + (long long)blockIdx.x * SEQ;
    const int tid = threadIdx.x;  // 256 x float4
    float4 v = reinterpret_cast<float4*>(p)[tid];
    v.x *= scale; v.y *= scale; v.z *= scale; v.w *= scale;
    float m = fmaxf(fmaxf(v.x, v.y), fmaxf(v.z, v.w));
    __shared__ float sh[8];
    __shared__ float s_bcast;
    for (int o = 16; o > 0; o >>= 1) m = fmaxf(m, __shfl_xor_sync(0xffffffffu, m, o));
    if ((tid & 31) == 0) sh[tid >> 5] = m;
    __syncthreads();
    if (tid == 0) {
        float mm = sh[0];
        for (int i = 1; i < 8; i++) mm = fmaxf(mm, sh[i]);
        s_bcast = mm;
    }
    __syncthreads();
    const float mm = s_bcast;
    float4 e;
    e.x = expf(v.x - mm); e.y = expf(v.y - mm);
    e.z = expf(v.z - mm); e.w = expf(v.w - mm);
    float s = e.x + e.y + e.z + e.w;
    for (int o = 16; o > 0; o >>= 1) s += __shfl_xor_sync(0xffffffffu, s, o);
    if ((tid & 31) == 0) sh[tid >> 5] = s;
    __syncthreads();
    if (tid == 0) {
        float ss = 0.f;
        for (int i = 0; i < 8; i++) ss += sh[i];
        s_bcast = 1.0f / ss;
    }
    __syncthreads();
    const float inv = s_bcast;
    e.x *= inv; e.y *= inv; e.z *= inv; e.w *= inv;
    reinterpret_cast<float4*>(p)[tid] = e;
}

// ---------------- zero moe accumulator + counters ----------------
__global__ void zero_k(float* __restrict__ moe, int* __restrict__ cnt) {
    long long i = (long long)blockIdx.x * blockDim.x + threadIdx.x;
    const long long n = (long long)TTOK * DMOD;
    for (; i < n; i += (long long)gridDim.x * blockDim.x) moe[i] = 0.f;
    if (blockIdx.x == 0 && threadIdx.x < NE) cnt[threadIdx.x] = 0;
}

// ---------------- gate: logits, top-2, softmax weights, bucket tokens ----------------
__global__ void gate_k(const float* __restrict__ x, const float* __restrict__ gw,
                       const float* __restrict__ gb, int* __restrict__ cnt,
                       int* __restrict__ perm, float* __restrict__ pw) {
    const int t = blockIdx.x;
    const int tid = threadIdx.x;  // 256
    float acc[NE];
#pragma unroll
    for (int e = 0; e < NE; e++) acc[e] = 0.f;
    for (int d = tid; d < DMOD; d += 256) {
        const float xv = x[(long long)t * DMOD + d];
        const float* grow = gw + (long long)d * NE;
#pragma unroll
        for (int e = 0; e < NE; e++) acc[e] += xv * grow[e];
    }
    __shared__ float sh[NE][8];
    const int lane = tid & 31, wid = tid >> 5;
#pragma unroll
    for (int e = 0; e < NE; e++) {
        float s = acc[e];
        for (int o = 16; o > 0; o >>= 1) s += __shfl_xor_sync(0xffffffffu, s, o);
        if (lane == 0) sh[e][wid] = s;
    }
    __syncthreads();
    if (tid == 0) {
        float lg[NE];
#pragma unroll
        for (int e = 0; e < NE; e++) {
            float s = 0.f;
            for (int w = 0; w < 8; w++) s += sh[e][w];
            lg[e] = s + gb[e];
        }
        int i0 = 0;
        for (int e = 1; e < NE; e++) if (lg[e] > lg[i0]) i0 = e;
        int i1 = (i0 == 0) ? 1 : 0;
        for (int e = 0; e < NE; e++) if (e != i0 && lg[e] > lg[i1]) i1 = e;
        const float e1 = expf(lg[i1] - lg[i0]);
        const float inv = 1.0f / (1.0f + e1);
        const float w0 = inv, w1 = e1 * inv;
        int p0 = atomicAdd(&cnt[i0], 1); perm[i0 * TTOK + p0] = t; pw[i0 * TTOK + p0] = w0;
        int p1 = atomicAdd(&cnt[i1], 1); perm[i1 * TTOK + p1] = t; pw[i1 * TTOK + p1] = w1;
    }
}

// ---------------- host orchestration ----------------
extern "C" void kernel_launch(void* const* d_in, const int* in_sizes, int n_in,
                              void* d_out, int out_size) {
    (void)in_sizes; (void)n_in; (void)out_size;
    const int*   src    = (const int*)  d_in[0];
    const float* emb    = (const float*)d_in[1];
    const float* Wq     = (const float*)d_in[2];
    const float* bq     = (const float*)d_in[3];
    const float* Wk     = (const float*)d_in[4];
    const float* bk     = (const float*)d_in[5];
    const float* Wv     = (const float*)d_in[6];
    const float* bv     = (const float*)d_in[7];
    const float* Wo     = (const float*)d_in[8];
    const float* bo     = (const float*)d_in[9];
    const float* ln1_g  = (const float*)d_in[10];
    const float* ln1_b  = (const float*)d_in[11];
    const float* W1     = (const float*)d_in[12];
    const float* b1     = (const float*)d_in[13];
    const float* W2     = (const float*)d_in[14];
    const float* b2     = (const float*)d_in[15];
    const float* ln2_g  = (const float*)d_in[16];
    const float* ln2_b  = (const float*)d_in[17];
    const float* gate_W = (const float*)d_in[18];
    const float* gate_b = (const float*)d_in[19];
    const float* eW1    = (const float*)d_in[20];
    const float* eb1    = (const float*)d_in[21];
    const float* eW2    = (const float*)d_in[22];
    const float* eb2    = (const float*)d_in[23];
    const float* fln_g  = (const float*)d_in[24];
    const float* fln_b  = (const float*)d_in[25];
    const float* out_W  = (const float*)d_in[26];
    const float* out_b  = (const float*)d_in[27];

    float *x, *q, *k, *v, *t1, *sc, *ffh, *moeh, *moe, *xn, *pw;
    int *cnt, *perm;
    cudaGetSymbolAddress((void**)&x,    g_x);
    cudaGetSymbolAddress((void**)&q,    g_q);
    cudaGetSymbolAddress((void**)&k,    g_k);
    cudaGetSymbolAddress((void**)&v,    g_v);
    cudaGetSymbolAddress((void**)&t1,   g_t1);
    cudaGetSymbolAddress((void**)&sc,   g_sc);
    cudaGetSymbolAddress((void**)&ffh,  g_ffh);
    cudaGetSymbolAddress((void**)&moeh, g_moeh);
    cudaGetSymbolAddress((void**)&moe,  g_moe);
    cudaGetSymbolAddress((void**)&xn,   g_xn);
    cudaGetSymbolAddress((void**)&pw,   g_pw);
    cudaGetSymbolAddress((void**)&cnt,  g_cnt);
    cudaGetSymbolAddress((void**)&perm, g_perm);

    embed_k<<<TTOK, 256>>>(src, emb, x);

    for (int l = 0; l < NL; l++) {
        GP p;
        // q / k / v projections
        const float* Ws[3]  = { Wq + (long long)l * DMOD * DMOD,
                                Wk + (long long)l * DMOD * DMOD,
                                Wv + (long long)l * DMOD * DMOD };
        const float* bs[3]  = { bq + l * DMOD, bk + l * DMOD, bv + l * DMOD };
        float*       Cs[3]  = { q, k, v };
        for (int m = 0; m < 3; m++) {
            p = GP{};
            p.A = x; p.B = Ws[m]; p.C = Cs[m]; p.bias = bs[m];
            p.M = TTOK; p.N = DMOD; p.K = DMOD;
            p.lda = DMOD; p.ldb = DMOD; p.ldc = DMOD; p.bh = 1;
            gemm_k<128,128,8,8,8,false,false,EP_STORE><<<dim3(8,16,1),256>>>(p);
        }
        // scores = q @ k^T (batched over b,h)
        p = GP{};
        p.A = q; p.B = k; p.C = sc;
        p.M = SEQ; p.N = SEQ; p.K = HDM;
        p.lda = DMOD; p.ldb = DMOD; p.ldc = SEQ;
        p.bh = NH;
        p.sA1 = HDM; p.sA2 = (long long)SEQ * DMOD;
        p.sB1 = HDM; p.sB2 = (long long)SEQ * DMOD;
        p.sC1 = (long long)SEQ * SEQ; p.sC2 = (long long)NH * SEQ * SEQ;
        gemm_k<128,128,8,8,8,true,false,EP_STORE><<<dim3(8,8,NBAT*NH),256>>>(p);
        // softmax
        softmax_k<<<NBAT*NH*SEQ, 256>>>(sc);
        // attnout = attn @ v   (into q buffer, re-merged head layout)
        p = GP{};
        p.A = sc; p.B = v; p.C = q;
        p.M = SEQ; p.N = HDM; p.K = SEQ;
        p.lda = SEQ; p.ldb = DMOD; p.ldc = DMOD;
        p.bh = NH;
        p.sA1 = (long long)SEQ * SEQ; p.sA2 = (long long)NH * SEQ * SEQ;
        p.sB1 = HDM; p.sB2 = (long long)SEQ * DMOD;
        p.sC1 = HDM; p.sC2 = (long long)SEQ * DMOD;
        gemm_k<128,64,8,8,4,false,false,EP_STORE><<<dim3(1,8,NBAT*NH),256>>>(p);
        // ao = attnout @ Wo + bo
        p = GP{};
        p.A = q; p.B = Wo + (long long)l * DMOD * DMOD; p.C = t1; p.bias = bo + l * DMOD;
        p.M = TTOK; p.N = DMOD; p.K = DMOD;
        p.lda = DMOD; p.ldb = DMOD; p.ldc = DMOD; p.bh = 1;
        gemm_k<128,128,8,8,8,false,false,EP_STORE><<<dim3(8,16,1),256>>>(p);
        // x = LN(x + ao)
        ln_k<<<TTOK, 256>>>(t1, x, ln1_g + l * DMOD, ln1_b + l * DMOD, x);
        // ffh = relu(x @ W1 + b1)
        p = GP{};
        p.A = x; p.B = W1 + (long long)l * DMOD * FDIM; p.C = ffh; p.bias = b1 + l * FDIM;
        p.M = TTOK; p.N = FDIM; p.K = DMOD;
        p.lda = DMOD; p.ldb = FDIM; p.ldc = FDIM; p.bh = 1;
        gemm_k<128,128,8,8,8,false,false,EP_RELU><<<dim3(32,16,1),256>>>(p);
        // ff = ffh @ W2 + b2
        p = GP{};
        p.A = ffh; p.B = W2 + (long long)l * FDIM * DMOD; p.C = t1; p.bias = b2 + l * DMOD;
        p.M = TTOK; p.N = DMOD; p.K = FDIM;
        p.lda = FDIM; p.ldb = DMOD; p.ldc = DMOD; p.bh = 1;
        gemm_k<128,128,8,8,8,false,false,EP_STORE><<<dim3(8,16,1),256>>>(p);
        // x = LN(x + ff)
        ln_k<<<TTOK, 256>>>(t1, x, ln2_g + l * DMOD, ln2_b + l * DMOD, x);
    }

    // MoE
    zero_k<<<2048, 256>>>(moe, cnt);
    gate_k<<<TTOK, 256>>>(x, gate_W, gate_b, cnt, perm, pw);
    {
        GP p = GP{};
        // expert hidden: gather rows of x, relu(x @ eW1 + eb1)
        p.A = x; p.B = eW1; p.C = moeh; p.bias = eb1;
        p.M = TTOK; p.N = FDIM; p.K = DMOD;
        p.lda = DMOD; p.ldb = FDIM; p.ldc = FDIM;
        p.bh = NE;
        p.sB1 = (long long)DMOD * FDIM; p.sC1 = (long long)TTOK * FDIM; p.sBias1 = FDIM;
        p.counts = cnt; p.rowmap = perm; p.mapStride = TTOK;
        gemm_k<128,128,8,8,8,false,true,EP_RELU><<<dim3(32,16,NE),256>>>(p);
    }
    {
        GP p = GP{};
        // expert out: (h @ eW2 + eb2), scaled scatter-add into moe
        p.A = moeh; p.B = eW2; p.bias = eb2;
        p.M = TTOK; p.N = DMOD; p.K = FDIM;
        p.lda = FDIM; p.ldb = DMOD;
        p.bh = NE;
        p.sA1 = (long long)TTOK * FDIM; p.sB1 = (long long)FDIM * DMOD; p.sBias1 = DMOD;
        p.counts = cnt; p.rowmap = perm; p.mapStride = TTOK;
        p.rowsc = pw; p.scat = moe; p.scat_ld = DMOD;
        gemm_k<128,128,8,8,8,false,false,EP_SCATTER><<<dim3(8,16,NE),256>>>(p);
    }
    // final layernorm
    ln_k<<<TTOK, 256>>>(moe, nullptr, fln_g, fln_b, xn);
    // output projection -> d_out
    {
        GP p = GP{};
        p.A = xn; p.B = out_W; p.C = (float*)d_out; p.bias = out_b;
        p.M = TTOK; p.N = VOC; p.K = DMOD;
        p.lda = DMOD; p.ldb = VOC; p.ldc = VOC; p.bh = 1;
        gemm_k<128,128,8,8,8,false,false,EP_STORE><<<dim3(250,16,1),256>>>(p);
    }
}

// round 3
// speedup vs baseline: 2.9788x; 2.9788x over previous
#include <cuda_runtime.h>
#include <cuda_fp16.h>
#include <math.h>
#include <stdint.h>
#include <string.h>

#define TTOK 2048
#define DMOD 1024
#define FDIM 4096
#define SEQ  1024
#define NBAT 2
#define NH   16
#define HDM  64
#define NE   8
#define VOC  32000
#define NL   3

// ---------------- scratch (static device globals; no allocation) ----------------
// split fp16 weights (hi, lo)
__device__ __half g_wq_h [NL*DMOD*DMOD], g_wq_l [NL*DMOD*DMOD];
__device__ __half g_wk_h [NL*DMOD*DMOD], g_wk_l [NL*DMOD*DMOD];
__device__ __half g_wv_h [NL*DMOD*DMOD], g_wv_l [NL*DMOD*DMOD];
__device__ __half g_wo_h [NL*DMOD*DMOD], g_wo_l [NL*DMOD*DMOD];
__device__ __half g_w1_h [NL*DMOD*FDIM], g_w1_l [NL*DMOD*FDIM];
__device__ __half g_w2_h [NL*FDIM*DMOD], g_w2_l [NL*FDIM*DMOD];
__device__ __half g_ew1_h[NE*DMOD*FDIM], g_ew1_l[NE*DMOD*FDIM];
__device__ __half g_ew2_h[NE*FDIM*DMOD], g_ew2_l[NE*FDIM*DMOD];
__device__ __half g_ow_h [DMOD*VOC],     g_ow_l [DMOD*VOC];
// split fp16 activations
__device__ __half g_x_h  [TTOK*DMOD], g_x_l  [TTOK*DMOD];
__device__ __half g_q_h  [TTOK*DMOD], g_q_l  [TTOK*DMOD];
__device__ __half g_k_h  [TTOK*DMOD], g_k_l  [TTOK*DMOD];
__device__ __half g_v_h  [TTOK*DMOD], g_v_l  [TTOK*DMOD];
__device__ __half g_ao_h [TTOK*DMOD], g_ao_l [TTOK*DMOD];
__device__ __half g_p_h  [NBAT*NH*SEQ*SEQ], g_p_l [NBAT*NH*SEQ*SEQ];
__device__ __half g_ffh_h[TTOK*FDIM], g_ffh_l[TTOK*FDIM];
__device__ __half g_mh_h [NE*TTOK*FDIM], g_mh_l [NE*TTOK*FDIM];
__device__ __half g_xn_h [TTOK*DMOD], g_xn_l [TTOK*DMOD];
// fp32 intermediates
__device__ float  g_xf  [TTOK*DMOD];
__device__ float  g_t1f [TTOK*DMOD];
__device__ float  g_scf [NBAT*NH*SEQ*SEQ];
__device__ float  g_moef[TTOK*DMOD];
__device__ float  g_xnf [TTOK*DMOD];
__device__ int    g_cnt [NE];
__device__ int    g_perm[NE*TTOK];
__device__ float  g_pw  [NE*TTOK];

// ---------------- PTX helpers ----------------
__device__ __forceinline__ uint32_t smem_u32(const void* p) {
    return (uint32_t)__cvta_generic_to_shared(p);
}
__device__ __forceinline__ void cp16(void* dst, const void* src, bool valid) {
    asm volatile("cp.async.ca.shared.global [%0], [%1], 16, %2;\n"
                 :: "r"(smem_u32(dst)), "l"(src), "r"(valid ? 16 : 0));
}
__device__ __forceinline__ void cp_commit() { asm volatile("cp.async.commit_group;\n"); }
__device__ __forceinline__ void cp_wait0()  { asm volatile("cp.async.wait_group 0;\n"); }
__device__ __forceinline__ void cp_wait1()  { asm volatile("cp.async.wait_group 1;\n"); }
__device__ __forceinline__ void ldsm4(uint32_t* r, uint32_t a) {
    asm volatile("ldmatrix.sync.aligned.m8n8.x4.shared.b16 {%0,%1,%2,%3},[%4];"
                 : "=r"(r[0]), "=r"(r[1]), "=r"(r[2]), "=r"(r[3]) : "r"(a));
}
__device__ __forceinline__ void ldsm4t(uint32_t* r, uint32_t a) {
    asm volatile("ldmatrix.sync.aligned.m8n8.x4.trans.shared.b16 {%0,%1,%2,%3},[%4];"
                 : "=r"(r[0]), "=r"(r[1]), "=r"(r[2]), "=r"(r[3]) : "r"(a));
}
__device__ __forceinline__ void mma16816(float* c, const uint32_t* a, const uint32_t* b) {
    asm volatile("mma.sync.aligned.m16n8k16.row.col.f32.f16.f16.f32 "
                 "{%0,%1,%2,%3},{%4,%5,%6,%7},{%8,%9},{%0,%1,%2,%3};"
                 : "+f"(c[0]), "+f"(c[1]), "+f"(c[2]), "+f"(c[3])
                 : "r"(a[0]), "r"(a[1]), "r"(a[2]), "r"(a[3]), "r"(b[0]), "r"(b[1]));
}
__device__ __forceinline__ void split2(float v0, float v1, __half2& h2, __half2& l2) {
    __half h0 = __float2half_rn(v0), h1 = __float2half_rn(v1);
    __half l0 = __float2half_rn(v0 - __half2float(h0));
    __half l1 = __float2half_rn(v1 - __half2float(h1));
    h2 = __halves2half2(h0, h1);
    l2 = __halves2half2(l0, l1);
}

// ---------------- fp32 -> (hi, lo) fp16 split ----------------
__global__ void split_k(const float* __restrict__ s, __half* __restrict__ h,
                        __half* __restrict__ l, long long n4) {
    long long i = (long long)blockIdx.x * blockDim.x + threadIdx.x;
    if (i >= n4) return;
    float4 v = reinterpret_cast<const float4*>(s)[i];
    __half2 h0, l0, h1, l1;
    split2(v.x, v.y, h0, l0);
    split2(v.z, v.w, h1, l1);
    reinterpret_cast<__half2*>(h)[i * 2 + 0] = h0;
    reinterpret_cast<__half2*>(h)[i * 2 + 1] = h1;
    reinterpret_cast<__half2*>(l)[i * 2 + 0] = l0;
    reinterpret_cast<__half2*>(l)[i * 2 + 1] = l1;
}

// ---------------- split-fp16 tensor-core GEMM (fp32-accurate) ----------------
struct HP {
    const __half *Ah, *Al, *Bh, *Bl;
    float* Cf; __half *Chi, *Clo;
    const float* bias;
    int M, N, K, lda, ldb, ldc, bh;
    long long sA1, sA2, sB1, sB2, sC1, sC2, sBias1;
    const int* counts; const int* rowmap; int mapStride;
    const float* rowsc; float* scat; int scat_ld;
};

enum { EP_F32 = 0, EP_SPLIT = 1, EP_SPLIT_RELU = 2, EP_SCATTER = 3 };

template<int BM, int BN, int WROWS, int WCOLS, bool TB, bool GATHER, int MODE>
__global__ __launch_bounds__(256) void hgemm_k(HP p) {
    constexpr int BK = 16;
    constexpr int WM = BM / WROWS, WN = BN / WCOLS;
    constexpr int MM = WM / 16, MN = WN / 8;
    constexpr int APAD = BK + 8, BPAD = BN + 8;
    static_assert(BM == 128, "loader assumes BM=128");

    const int z  = blockIdx.z;
    const int b2 = z / p.bh, b1 = z % p.bh;
    const __half* Ah = p.Ah + b2 * p.sA2 + b1 * p.sA1;
    const __half* Al = p.Al + b2 * p.sA2 + b1 * p.sA1;
    const __half* Bh = p.Bh + b2 * p.sB2 + b1 * p.sB1;
    const __half* Bl = p.Bl + b2 * p.sB2 + b1 * p.sB1;
    const int M = p.counts ? p.counts[z] : p.M;
    const int row0 = blockIdx.y * BM;
    if (row0 >= M) return;
    const int col0 = blockIdx.x * BN;

    __shared__ __half Ash[2][BM][APAD], Asl[2][BM][APAD];
    __shared__ __half Bsh[2][BK][BPAD], Bsl[2][BK][BPAD];

    const int tid = threadIdx.x;
    const int l   = tid & 31;
    const int wid = tid >> 5;
    const int wr  = wid / WCOLS, wc = wid % WCOLS;

    const int* rmap = (GATHER || MODE == EP_SCATTER)
                      ? p.rowmap + (long long)z * p.mapStride : nullptr;

    float acc[MM][MN][4];
#pragma unroll
    for (int i = 0; i < MM; i++)
#pragma unroll
        for (int j = 0; j < MN; j++)
#pragma unroll
            for (int r = 0; r < 4; r++) acc[i][j][r] = 0.f;

    // A loader: BM*BK/8 = 256 chunks per array -> 1 per thread
    const int aRow = tid >> 1, aK = (tid & 1) * 8;
    const bool aValid = (row0 + aRow) < M;
    long long aBase;
    if (GATHER) {
        int tok = aValid ? rmap[row0 + aRow] : 0;
        aBase = (long long)tok * p.lda;
    } else {
        aBase = (long long)(row0 + aRow) * p.lda;
    }
    auto loadA = [&](int kt, int st) {
        const int k0 = kt * BK;
        cp16(&Ash[st][aRow][aK], Ah + aBase + k0 + aK, aValid);
        cp16(&Asl[st][aRow][aK], Al + aBase + k0 + aK, aValid);
    };
    auto loadB = [&](int kt, int st) {
        constexpr int CHB = BK * BN / 8;   // 256 (BN=128) or 128 (BN=64)
        const int k0 = kt * BK;
        if (CHB == 256 || tid < CHB) {
            const int row = tid / (BN / 8), n8 = (tid % (BN / 8)) * 8;
            cp16(&Bsh[st][row][n8], Bh + (long long)(k0 + row) * p.ldb + col0 + n8, true);
            cp16(&Bsl[st][row][n8], Bl + (long long)(k0 + row) * p.ldb + col0 + n8, true);
        }
    };
    auto loadBt = [&](int kt, int st) {  // B stored [N][K]; Bs[k][n] = B[n][k] (BN=128)
        const int k0 = kt * BK;
        const int n = tid >> 1, k8 = (tid & 1) * 8;
        uint4 rh = *reinterpret_cast<const uint4*>(Bh + (long long)(col0 + n) * p.ldb + k0 + k8);
        uint4 rl = *reinterpret_cast<const uint4*>(Bl + (long long)(col0 + n) * p.ldb + k0 + k8);
        __half hh[8], ll[8];
        memcpy(hh, &rh, 16); memcpy(ll, &rl, 16);
#pragma unroll
        for (int j = 0; j < 8; j++) { Bsh[st][k8 + j][n] = hh[j]; Bsl[st][k8 + j][n] = ll[j]; }
    };

    auto compute = [&](int st) {
        uint32_t fah[MM][4], fal[MM][4], fbh[MN][2], fbl[MN][2];
#pragma unroll
        for (int mi = 0; mi < MM; mi++) {
            const int r = wr * WM + mi * 16 + (l & 15);
            const int c = (l >> 4) << 3;
            ldsm4(fah[mi], smem_u32(&Ash[st][r][c]));
            ldsm4(fal[mi], smem_u32(&Asl[st][r][c]));
        }
#pragma unroll
        for (int nj = 0; nj < MN / 2; nj++) {
            const int r = l & 15;
            const int c = wc * WN + nj * 16 + ((l >> 4) << 3);
            uint32_t r4[4];
            ldsm4t(r4, smem_u32(&Bsh[st][r][c]));
            fbh[2*nj][0] = r4[0]; fbh[2*nj][1] = r4[1];
            fbh[2*nj+1][0] = r4[2]; fbh[2*nj+1][1] = r4[3];
            ldsm4t(r4, smem_u32(&Bsl[st][r][c]));
            fbl[2*nj][0] = r4[0]; fbl[2*nj][1] = r4[1];
            fbl[2*nj+1][0] = r4[2]; fbl[2*nj+1][1] = r4[3];
        }
#pragma unroll
        for (int mi = 0; mi < MM; mi++)
#pragma unroll
            for (int ni = 0; ni < MN; ni++) {
                mma16816(acc[mi][ni], fah[mi], fbh[ni]);   // hi*hi
                mma16816(acc[mi][ni], fah[mi], fbl[ni]);   // hi*lo
                mma16816(acc[mi][ni], fal[mi], fbh[ni]);   // lo*hi
            }
    };

    const int nK = p.K / BK;
    if (TB) {
        for (int kt = 0; kt < nK; kt++) {
            loadA(kt, 0); cp_commit();
            loadBt(kt, 0);
            cp_wait0();
            __syncthreads();
            compute(0);
            __syncthreads();
        }
    } else {
        loadA(0, 0); loadB(0, 0); cp_commit();
        for (int kt = 0; kt < nK; kt++) {
            const int st = kt & 1;
            if (kt + 1 < nK) {
                loadA(kt + 1, st ^ 1); loadB(kt + 1, st ^ 1); cp_commit();
                cp_wait1();
            } else {
                cp_wait0();
            }
            __syncthreads();
            compute(st);
            __syncthreads();
        }
    }

    // ---- epilogue ----
    const float* bias = p.bias ? p.bias + b1 * p.sBias1 : nullptr;
    float*  Cf  = p.Cf  ? p.Cf  + b2 * p.sC2 + b1 * p.sC1 : nullptr;
    __half* Chi = p.Chi ? p.Chi + b2 * p.sC2 + b1 * p.sC1 : nullptr;
    __half* Clo = p.Clo ? p.Clo + b2 * p.sC2 + b1 * p.sC1 : nullptr;
#pragma unroll
    for (int mi = 0; mi < MM; mi++) {
#pragma unroll
        for (int hh = 0; hh < 2; hh++) {
            const int r = row0 + wr * WM + mi * 16 + (l >> 2) + hh * 8;
            if (r >= M) continue;
#pragma unroll
            for (int ni = 0; ni < MN; ni++) {
                const int c = col0 + wc * WN + ni * 8 + (l & 3) * 2;
                float v0 = acc[mi][ni][hh * 2 + 0];
                float v1 = acc[mi][ni][hh * 2 + 1];
                if (bias) { v0 += bias[c]; v1 += bias[c + 1]; }
                if (MODE == EP_SPLIT_RELU) { v0 = fmaxf(v0, 0.f); v1 = fmaxf(v1, 0.f); }
                if (MODE == EP_SCATTER) {
                    const int tok = rmap[r];
                    const float w = p.rowsc[(long long)z * p.mapStride + r];
                    atomicAdd(p.scat + (long long)tok * p.scat_ld + c,     w * v0);
                    atomicAdd(p.scat + (long long)tok * p.scat_ld + c + 1, w * v1);
                } else if (MODE == EP_F32) {
                    *reinterpret_cast<float2*>(Cf + (long long)r * p.ldc + c) =
                        make_float2(v0, v1);
                } else {
                    __half2 h2, l2;
                    split2(v0, v1, h2, l2);
                    *reinterpret_cast<__half2*>(Chi + (long long)r * p.ldc + c) = h2;
                    *reinterpret_cast<__half2*>(Clo + (long long)r * p.ldc + c) = l2;
                }
            }
        }
    }
}

// ---------------- embedding + positional encoding ----------------
__global__ void embed_k(const int* __restrict__ src, const float* __restrict__ emb,
                        float* __restrict__ xf, __half* __restrict__ xh,
                        __half* __restrict__ xl) {
    const int t = blockIdx.x;
    const int s = t % SEQ;
    const int tok = src[t];
    const float c = -logf(10000.0f) / (float)DMOD;
    for (int d = threadIdx.x; d < DMOD; d += blockDim.x) {
        const int i = d >> 1;
        const float div = expf((float)(2 * i) * c);
        const float ang = (float)s * div;
        const float pe = (d & 1) ? cosf(ang) : sinf(ang);
        const float v = emb[(long long)tok * DMOD + d] * 32.0f + pe;
        xf[(long long)t * DMOD + d] = v;
        __half h = __float2half_rn(v);
        xh[(long long)t * DMOD + d] = h;
        xl[(long long)t * DMOD + d] = __float2half_rn(v - __half2float(h));
    }
}

// ---------------- layernorm: out = LN(a (+ res)), writes fp32 + split ----------------
__global__ void ln_k(const float* __restrict__ a, const float* __restrict__ res,
                     const float* __restrict__ g, const float* __restrict__ be,
                     float* __restrict__ of, __half* __restrict__ oh,
                     __half* __restrict__ ol) {
    const int row = blockIdx.x;
    const int tid = threadIdx.x;  // 256 threads x 4 elems
    float4 v = reinterpret_cast<const float4*>(a + (long long)row * DMOD)[tid];
    if (res) {
        float4 r = reinterpret_cast<const float4*>(res + (long long)row * DMOD)[tid];
        v.x += r.x; v.y += r.y; v.z += r.z; v.w += r.w;
    }
    float s  = v.x + v.y + v.z + v.w;
    float sq = v.x*v.x + v.y*v.y + v.z*v.z + v.w*v.w;
    __shared__ float rs[8], rq[8];
    for (int o = 16; o > 0; o >>= 1) {
        s  += __shfl_xor_sync(0xffffffffu, s,  o);
        sq += __shfl_xor_sync(0xffffffffu, sq, o);
    }
    if ((tid & 31) == 0) { rs[tid >> 5] = s; rq[tid >> 5] = sq; }
    __syncthreads();
    __shared__ float s_mu, s_inv;
    if (tid == 0) {
        float S = 0.f, Q = 0.f;
        for (int i = 0; i < 8; i++) { S += rs[i]; Q += rq[i]; }
        const float mu  = S / (float)DMOD;
        const float var = Q / (float)DMOD - mu * mu;
        s_mu = mu; s_inv = rsqrtf(var + 1e-5f);
    }
    __syncthreads();
    const float mu = s_mu, inv = s_inv;
    const float4 gv = reinterpret_cast<const float4*>(g)[tid];
    const float4 bv = reinterpret_cast<const float4*>(be)[tid];
    float o0 = (v.x - mu) * inv * gv.x + bv.x;
    float o1 = (v.y - mu) * inv * gv.y + bv.y;
    float o2 = (v.z - mu) * inv * gv.z + bv.z;
    float o3 = (v.w - mu) * inv * gv.w + bv.w;
    if (of) reinterpret_cast<float4*>(of + (long long)row * DMOD)[tid] = make_float4(o0, o1, o2, o3);
    __half2 h0, l0, h1, l1;
    split2(o0, o1, h0, l0);
    split2(o2, o3, h1, l1);
    reinterpret_cast<__half2*>(oh + (long long)row * DMOD)[tid * 2 + 0] = h0;
    reinterpret_cast<__half2*>(oh + (long long)row * DMOD)[tid * 2 + 1] = h1;
    reinterpret_cast<__half2*>(ol + (long long)row * DMOD)[tid * 2 + 0] = l0;
    reinterpret_cast<__half2*>(ol + (long long)row * DMOD)[tid * 2 + 1] = l1;
}

// ---------------- softmax over fp32 scores -> split probs ----------------
__global__ void softmax_k(const float* __restrict__ scf, __half* __restrict__ ph,
                          __half* __restrict__ pl) {
    const float scale = 0.125f;
    const float* p = scf + (long long)blockIdx.x * SEQ;
    const int tid = threadIdx.x;  // 256 x 4
    float4 v = reinterpret_cast<const float4*>(p)[tid];
    v.x *= scale; v.y *= scale; v.z *= scale; v.w *= scale;
    float m = fmaxf(fmaxf(v.x, v.y), fmaxf(v.z, v.w));
    __shared__ float sh[8];
    __shared__ float s_bcast;
    for (int o = 16; o > 0; o >>= 1) m = fmaxf(m, __shfl_xor_sync(0xffffffffu, m, o));
    if ((tid & 31) == 0) sh[tid >> 5] = m;
    __syncthreads();
    if (tid == 0) {
        float mm = sh[0];
        for (int i = 1; i < 8; i++) mm = fmaxf(mm, sh[i]);
        s_bcast = mm;
    }
    __syncthreads();
    const float mm = s_bcast;
    float e0 = expf(v.x - mm), e1 = expf(v.y - mm), e2 = expf(v.z - mm), e3 = expf(v.w - mm);
    float ssum = e0 + e1 + e2 + e3;
    for (int o = 16; o > 0; o >>= 1) ssum += __shfl_xor_sync(0xffffffffu, ssum, o);
    if ((tid & 31) == 0) sh[tid >> 5] = ssum;
    __syncthreads();
    if (tid == 0) {
        float S = 0.f;
        for (int i = 0; i < 8; i++) S += sh[i];
        s_bcast = 1.0f / S;
    }
    __syncthreads();
    const float inv = s_bcast;
    e0 *= inv; e1 *= inv; e2 *= inv; e3 *= inv;
    __half2 h0, l0, h1, l1;
    split2(e0, e1, h0, l0);
    split2(e2, e3, h1, l1);
    const long long base = (long long)blockIdx.x * SEQ;
    reinterpret_cast<__half2*>(ph + base)[tid * 2 + 0] = h0;
    reinterpret_cast<__half2*>(ph + base)[tid * 2 + 1] = h1;
    reinterpret_cast<__half2*>(pl + base)[tid * 2 + 0] = l0;
    reinterpret_cast<__half2*>(pl + base)[tid * 2 + 1] = l1;
}

// ---------------- zero moe accumulator + counters ----------------
__global__ void zero_k(float* __restrict__ moe, int* __restrict__ cnt) {
    long long i = (long long)blockIdx.x * blockDim.x + threadIdx.x;
    const long long n = (long long)TTOK * DMOD;
    for (; i < n; i += (long long)gridDim.x * blockDim.x) moe[i] = 0.f;
    if (blockIdx.x == 0 && threadIdx.x < NE) cnt[threadIdx.x] = 0;
}

// ---------------- gate: top-2 + softmax weights + bucket tokens (fp32 x) ----------------
__global__ void gate_k(const float* __restrict__ x, const float* __restrict__ gw,
                       const float* __restrict__ gb, int* __restrict__ cnt,
                       int* __restrict__ perm, float* __restrict__ pw) {
    const int t = blockIdx.x;
    const int tid = threadIdx.x;
    float acc[NE];
#pragma unroll
    for (int e = 0; e < NE; e++) acc[e] = 0.f;
    for (int d = tid; d < DMOD; d += 256) {
        const float xv = x[(long long)t * DMOD + d];
        const float* grow = gw + (long long)d * NE;
#pragma unroll
        for (int e = 0; e < NE; e++) acc[e] += xv * grow[e];
    }
    __shared__ float sh[NE][8];
    const int lane = tid & 31, wid = tid >> 5;
#pragma unroll
    for (int e = 0; e < NE; e++) {
        float s = acc[e];
        for (int o = 16; o > 0; o >>= 1) s += __shfl_xor_sync(0xffffffffu, s, o);
        if (lane == 0) sh[e][wid] = s;
    }
    __syncthreads();
    if (tid == 0) {
        float lg[NE];
#pragma unroll
        for (int e = 0; e < NE; e++) {
            float s = 0.f;
            for (int w = 0; w < 8; w++) s += sh[e][w];
            lg[e] = s + gb[e];
        }
        int i0 = 0;
        for (int e = 1; e < NE; e++) if (lg[e] > lg[i0]) i0 = e;
        int i1 = (i0 == 0) ? 1 : 0;
        for (int e = 0; e < NE; e++) if (e != i0 && lg[e] > lg[i1]) i1 = e;
        const float e1 = expf(lg[i1] - lg[i0]);
        const float inv = 1.0f / (1.0f + e1);
        int p0 = atomicAdd(&cnt[i0], 1); perm[i0 * TTOK + p0] = t; pw[i0 * TTOK + p0] = inv;
        int p1 = atomicAdd(&cnt[i1], 1); perm[i1 * TTOK + p1] = t; pw[i1 * TTOK + p1] = e1 * inv;
    }
}

// ---------------- host orchestration ----------------
static inline void splitw(const float* s, __half* h, __half* l, long long n) {
    long long n4 = n / 4;
    split_k<<<(unsigned)((n4 + 255) / 256), 256>>>(s, h, l, n4);
}

extern "C" void kernel_launch(void* const* d_in, const int* in_sizes, int n_in,
                              void* d_out, int out_size) {
    (void)in_sizes; (void)n_in; (void)out_size;
    const int*   src    = (const int*)  d_in[0];
    const float* emb    = (const float*)d_in[1];
    const float* Wq     = (const float*)d_in[2];
    const float* bq     = (const float*)d_in[3];
    const float* Wk     = (const float*)d_in[4];
    const float* bk     = (const float*)d_in[5];
    const float* Wv     = (const float*)d_in[6];
    const float* bv     = (const float*)d_in[7];
    const float* Wo     = (const float*)d_in[8];
    const float* bo     = (const float*)d_in[9];
    const float* ln1_g  = (const float*)d_in[10];
    const float* ln1_b  = (const float*)d_in[11];
    const float* W1     = (const float*)d_in[12];
    const float* b1     = (const float*)d_in[13];
    const float* W2     = (const float*)d_in[14];
    const float* b2     = (const float*)d_in[15];
    const float* ln2_g  = (const float*)d_in[16];
    const float* ln2_b  = (const float*)d_in[17];
    const float* gate_W = (const float*)d_in[18];
    const float* gate_b = (const float*)d_in[19];
    const float* eW1    = (const float*)d_in[20];
    const float* eb1    = (const float*)d_in[21];
    const float* eW2    = (const float*)d_in[22];
    const float* eb2    = (const float*)d_in[23];
    const float* fln_g  = (const float*)d_in[24];
    const float* fln_b  = (const float*)d_in[25];
    const float* out_W  = (const float*)d_in[26];
    const float* out_b  = (const float*)d_in[27];

#define SYM(v, s) cudaGetSymbolAddress((void**)&v, s)
    __half *wq_h,*wq_l,*wk_h,*wk_l,*wv_h,*wv_l,*wo_h,*wo_l;
    __half *w1_h,*w1_l,*w2_h,*w2_l,*ew1_h,*ew1_l,*ew2_h,*ew2_l,*ow_h,*ow_l;
    __half *x_h,*x_l,*q_h,*q_l,*k_h,*k_l,*v_h,*v_l,*ao_h,*ao_l;
    __half *p_h,*p_l,*ffh_h,*ffh_l,*mh_h,*mh_l,*xn_h,*xn_l;
    float *xf,*t1f,*scf,*moef,*xnf,*pw;
    int *cnt,*perm;
    SYM(wq_h,g_wq_h); SYM(wq_l,g_wq_l); SYM(wk_h,g_wk_h); SYM(wk_l,g_wk_l);
    SYM(wv_h,g_wv_h); SYM(wv_l,g_wv_l); SYM(wo_h,g_wo_h); SYM(wo_l,g_wo_l);
    SYM(w1_h,g_w1_h); SYM(w1_l,g_w1_l); SYM(w2_h,g_w2_h); SYM(w2_l,g_w2_l);
    SYM(ew1_h,g_ew1_h); SYM(ew1_l,g_ew1_l); SYM(ew2_h,g_ew2_h); SYM(ew2_l,g_ew2_l);
    SYM(ow_h,g_ow_h); SYM(ow_l,g_ow_l);
    SYM(x_h,g_x_h); SYM(x_l,g_x_l); SYM(q_h,g_q_h); SYM(q_l,g_q_l);
    SYM(k_h,g_k_h); SYM(k_l,g_k_l); SYM(v_h,g_v_h); SYM(v_l,g_v_l);
    SYM(ao_h,g_ao_h); SYM(ao_l,g_ao_l); SYM(p_h,g_p_h); SYM(p_l,g_p_l);
    SYM(ffh_h,g_ffh_h); SYM(ffh_l,g_ffh_l); SYM(mh_h,g_mh_h); SYM(mh_l,g_mh_l);
    SYM(xn_h,g_xn_h); SYM(xn_l,g_xn_l);
    SYM(xf,g_xf); SYM(t1f,g_t1f); SYM(scf,g_scf); SYM(moef,g_moef); SYM(xnf,g_xnf);
    SYM(pw,g_pw); SYM(cnt,g_cnt); SYM(perm,g_perm);
#undef SYM

    // weight conversions fp32 -> (hi, lo)
    splitw(Wq,  wq_h,  wq_l,  (long long)NL * DMOD * DMOD);
    splitw(Wk,  wk_h,  wk_l,  (long long)NL * DMOD * DMOD);
    splitw(Wv,  wv_h,  wv_l,  (long long)NL * DMOD * DMOD);
    splitw(Wo,  wo_h,  wo_l,  (long long)NL * DMOD * DMOD);
    splitw(W1,  w1_h,  w1_l,  (long long)NL * DMOD * FDIM);
    splitw(W2,  w2_h,  w2_l,  (long long)NL * FDIM * DMOD);
    splitw(eW1, ew1_h, ew1_l, (long long)NE * DMOD * FDIM);
    splitw(eW2, ew2_h, ew2_l, (long long)NE * FDIM * DMOD);
    splitw(out_W, ow_h, ow_l, (long long)DMOD * VOC);

    embed_k<<<TTOK, 256>>>(src, emb, xf, x_h, x_l);

    for (int l = 0; l < NL; l++) {
        HP p;
        const __half* Wh[3] = { wq_h + (long long)l*DMOD*DMOD, wk_h + (long long)l*DMOD*DMOD,
                                wv_h + (long long)l*DMOD*DMOD };
        const __half* Wl[3] = { wq_l + (long long)l*DMOD*DMOD, wk_l + (long long)l*DMOD*DMOD,
                                wv_l + (long long)l*DMOD*DMOD };
        const float*  bs[3] = { bq + l*DMOD, bk + l*DMOD, bv + l*DMOD };
        __half* Ch[3] = { q_h, k_h, v_h };
        __half* Cl[3] = { q_l, k_l, v_l };
        for (int m = 0; m < 3; m++) {
            p = HP{};
            p.Ah = x_h; p.Al = x_l; p.Bh = Wh[m]; p.Bl = Wl[m];
            p.Chi = Ch[m]; p.Clo = Cl[m]; p.bias = bs[m];
            p.M = TTOK; p.N = DMOD; p.K = DMOD;
            p.lda = DMOD; p.ldb = DMOD; p.ldc = DMOD; p.bh = 1;
            hgemm_k<128,128,2,4,false,false,EP_SPLIT><<<dim3(8,16,1),256>>>(p);
        }
        // scores = q @ k^T (fp32 out)
        p = HP{};
        p.Ah = q_h; p.Al = q_l; p.Bh = k_h; p.Bl = k_l; p.Cf = scf;
        p.M = SEQ; p.N = SEQ; p.K = HDM;
        p.lda = DMOD; p.ldb = DMOD; p.ldc = SEQ; p.bh = NH;
        p.sA1 = HDM; p.sA2 = (long long)SEQ * DMOD;
        p.sB1 = HDM; p.sB2 = (long long)SEQ * DMOD;
        p.sC1 = (long long)SEQ * SEQ; p.sC2 = (long long)NH * SEQ * SEQ;
        hgemm_k<128,128,2,4,true,false,EP_F32><<<dim3(8,8,NBAT*NH),256>>>(p);
        softmax_k<<<NBAT*NH*SEQ, 256>>>(scf, p_h, p_l);
        // attnout = attn @ v (split out, merged-head layout)
        p = HP{};
        p.Ah = p_h; p.Al = p_l; p.Bh = v_h; p.Bl = v_l; p.Chi = ao_h; p.Clo = ao_l;
        p.M = SEQ; p.N = HDM; p.K = SEQ;
        p.lda = SEQ; p.ldb = DMOD; p.ldc = DMOD; p.bh = NH;
        p.sA1 = (long long)SEQ * SEQ; p.sA2 = (long long)NH * SEQ * SEQ;
        p.sB1 = HDM; p.sB2 = (long long)SEQ * DMOD;
        p.sC1 = HDM; p.sC2 = (long long)SEQ * DMOD;
        hgemm_k<128,64,4,2,false,false,EP_SPLIT><<<dim3(1,8,NBAT*NH),256>>>(p);
        // ao @ Wo + bo (fp32 out)
        p = HP{};
        p.Ah = ao_h; p.Al = ao_l;
        p.Bh = wo_h + (long long)l*DMOD*DMOD; p.Bl = wo_l + (long long)l*DMOD*DMOD;
        p.Cf = t1f; p.bias = bo + l*DMOD;
        p.M = TTOK; p.N = DMOD; p.K = DMOD;
        p.lda = DMOD; p.ldb = DMOD; p.ldc = DMOD; p.bh = 1;
        hgemm_k<128,128,2,4,false,false,EP_F32><<<dim3(8,16,1),256>>>(p);
        ln_k<<<TTOK, 256>>>(t1f, xf, ln1_g + l*DMOD, ln1_b + l*DMOD, xf, x_h, x_l);
        // ffh = relu(x @ W1 + b1) (split out)
        p = HP{};
        p.Ah = x_h; p.Al = x_l;
        p.Bh = w1_h + (long long)l*DMOD*FDIM; p.Bl = w1_l + (long long)l*DMOD*FDIM;
        p.Chi = ffh_h; p.Clo = ffh_l; p.bias = b1 + l*FDIM;
        p.M = TTOK; p.N = FDIM; p.K = DMOD;
        p.lda = DMOD; p.ldb = FDIM; p.ldc = FDIM; p.bh = 1;
        hgemm_k<128,128,2,4,false,false,EP_SPLIT_RELU><<<dim3(32,16,1),256>>>(p);
        // ff = ffh @ W2 + b2 (fp32 out)
        p = HP{};
        p.Ah = ffh_h; p.Al = ffh_l;
        p.Bh = w2_h + (long long)l*FDIM*DMOD; p.Bl = w2_l + (long long)l*FDIM*DMOD;
        p.Cf = t1f; p.bias = b2 + l*DMOD;
        p.M = TTOK; p.N = DMOD; p.K = FDIM;
        p.lda = FDIM; p.ldb = DMOD; p.ldc = DMOD; p.bh = 1;
        hgemm_k<128,128,2,4,false,false,EP_F32><<<dim3(8,16,1),256>>>(p);
        ln_k<<<TTOK, 256>>>(t1f, xf, ln2_g + l*DMOD, ln2_b + l*DMOD, xf, x_h, x_l);
    }

    // MoE
    zero_k<<<2048, 256>>>(moef, cnt);
    gate_k<<<TTOK, 256>>>(xf, gate_W, gate_b, cnt, perm, pw);
    {
        HP p = HP{};
        p.Ah = x_h; p.Al = x_l; p.Bh = ew1_h; p.Bl = ew1_l;
        p.Chi = mh_h; p.Clo = mh_l; p.bias = eb1;
        p.M = TTOK; p.N = FDIM; p.K = DMOD;
        p.lda = DMOD; p.ldb = FDIM; p.ldc = FDIM; p.bh = NE;
        p.sB1 = (long long)DMOD * FDIM; p.sC1 = (long long)TTOK * FDIM; p.sBias1 = FDIM;
        p.counts = cnt; p.rowmap = perm; p.mapStride = TTOK;
        hgemm_k<128,128,2,4,false,true,EP_SPLIT_RELU><<<dim3(32,16,NE),256>>>(p);
    }
    {
        HP p = HP{};
        p.Ah = mh_h; p.Al = mh_l; p.Bh = ew2_h; p.Bl = ew2_l; p.bias = eb2;
        p.M = TTOK; p.N = DMOD; p.K = FDIM;
        p.lda = FDIM; p.ldb = DMOD; p.bh = NE;
        p.sA1 = (long long)TTOK * FDIM; p.sB1 = (long long)FDIM * DMOD; p.sBias1 = DMOD;
        p.counts = cnt; p.rowmap = perm; p.mapStride = TTOK;
        p.rowsc = pw; p.scat = moef; p.scat_ld = DMOD;
        hgemm_k<128,128,2,4,false,false,EP_SCATTER><<<dim3(8,16,NE),256>>>(p);
    }
    ln_k<<<TTOK, 256>>>(moef, nullptr, fln_g, fln_b, xnf, xn_h, xn_l);
    // output projection -> d_out (fp32)
    {
        HP p = HP{};
        p.Ah = xn_h; p.Al = xn_l; p.Bh = ow_h; p.Bl = ow_l;
        p.Cf = (float*)d_out; p.bias = out_b;
        p.M = TTOK; p.N = VOC; p.K = DMOD;
        p.lda = DMOD; p.ldb = VOC; p.ldc = VOC; p.bh = 1;
        hgemm_k<128,128,2,4,false,false,EP_F32><<<dim3(250,16,1),256>>>(p);
    }
}